// round 2
// baseline (speedup 1.0000x reference)
#include <cuda_runtime.h>
#include <cstdint>

#define B_ 4096
#define T_ 120
#define I_ 64
#define H_ 128
#define G_ 384   // 3*H

// 755 MB scratch for precomputed input-side gate pre-activations,
// stored gate-interleaved: xg[row][j*3 + gate], gate in {r=0,z=1,n=2}
__device__ float g_xg[(size_t)B_ * T_ * G_];

// ---- packed f32x2 helpers (ptxas will not auto-generate FFMA2) ----
#define FMA2(d, a, b) \
    asm("fma.rn.f32x2 %0, %1, %2, %0;" : "+l"(d) : "l"(a), "l"(b))

#define PACK2(p, f) do {                                            \
    unsigned int _u = __float_as_uint(f);                           \
    asm("mov.b64 %0, {%1, %2};" : "=l"(p) : "r"(_u), "r"(_u));      \
} while (0)

#define UNPACK2(lo, hi, p) do {                                     \
    unsigned int _l, _h;                                            \
    asm("mov.b64 {%0, %1}, %2;" : "=r"(_l), "=r"(_h) : "l"(p));     \
    (lo) = __uint_as_float(_l); (hi) = __uint_as_float(_h);         \
} while (0)

__device__ __forceinline__ float sigmoidf_(float x) {
    return __fdividef(1.0f, 1.0f + __expf(-x));
}
__device__ __forceinline__ float tanhf_(float x) {
    // tanh(x) = 1 - 2/(1 + e^{2x}); robust at +-inf via __expf saturation
    return 1.0f - __fdividef(2.0f, 1.0f + __expf(2.0f * x));
}

// =====================================================================
// Kernel 1: x_gates = x @ W_ih^T + b_ih  -> g_xg (gate-interleaved cols)
// CTA: 128 rows x 384 cols, 256 threads, thread tile 8x12, two col halves
// =====================================================================
#define K1_SMEM ((64 * G_ + 64 * 132 + G_) * 4)

__global__ __launch_bounds__(256, 1) void k1_xgates(
    const float* __restrict__ x,
    const float* __restrict__ Wih,
    const float* __restrict__ bih)
{
    extern __shared__ float sm[];
    float* Wt = sm;               // [64][384]  WihT[i][col']
    float* xT = Wt + 64 * G_;     // [64][132]  xT[i][row]
    float* bI = xT + 64 * 132;    // [384]

    const int tid = threadIdx.x;
    const size_t r0 = (size_t)blockIdx.x * 128;

    // Load W_ih reordered+transposed: col' = j*3 + gate, g = gate*128 + j
    for (int idx = tid; idx < G_ * I_; idx += 256) {
        int g = idx >> 6, i = idx & 63;
        Wt[i * G_ + ((g & 127) * 3 + (g >> 7))] = Wih[idx];
    }
    for (int g = tid; g < G_; g += 256)              // FIX: was `if (tid < G_)`
        bI[(g & 127) * 3 + (g >> 7)] = bih[g];
    // Load x tile transposed
    for (int idx = tid; idx < 128 * I_; idx += 256) {
        int r = idx >> 6, i = idx & 63;
        xT[i * 132 + r] = x[(r0 + r) * I_ + i];
    }
    __syncthreads();

    const int mblk = tid & 15;       // 16 row blocks of 8
    const int jblk = tid >> 4;       // 16 col blocks of 12 (per half)
    const int m0 = mblk * 8;

    for (int half = 0; half < 2; half++) {
        const int c0 = half * 192 + jblk * 12;

        unsigned long long acc[4][12];
        #pragma unroll
        for (int p = 0; p < 4; p++)
            #pragma unroll
            for (int c = 0; c < 12; c++) acc[p][c] = 0ull;

        #pragma unroll 4
        for (int k = 0; k < 64; k++) {
            const float* hrow = xT + k * 132 + m0;
            ulonglong2 ha = *(const ulonglong2*)(hrow);      // rows m0..m0+3
            ulonglong2 hb = *(const ulonglong2*)(hrow + 4);  // rows m0+4..m0+7
            const float* wrow = Wt + k * G_ + c0;
            float4 w0 = *(const float4*)(wrow);
            float4 w1 = *(const float4*)(wrow + 4);
            float4 w2 = *(const float4*)(wrow + 8);
            float wf[12] = {w0.x, w0.y, w0.z, w0.w,
                            w1.x, w1.y, w1.z, w1.w,
                            w2.x, w2.y, w2.z, w2.w};
            unsigned long long wp[12];
            #pragma unroll
            for (int c = 0; c < 12; c++) PACK2(wp[c], wf[c]);
            #pragma unroll
            for (int c = 0; c < 12; c++) {
                FMA2(acc[0][c], ha.x, wp[c]);
                FMA2(acc[1][c], ha.y, wp[c]);
                FMA2(acc[2][c], hb.x, wp[c]);
                FMA2(acc[3][c], hb.y, wp[c]);
            }
        }

        // Epilogue: unpack, add bias, store rows (m0+2p, m0+2p+1)
        #pragma unroll
        for (int p = 0; p < 4; p++) {
            float lo[12], hi[12];
            #pragma unroll
            for (int c = 0; c < 12; c++) {
                UNPACK2(lo[c], hi[c], acc[p][c]);
                float bb = bI[c0 + c];
                lo[c] += bb; hi[c] += bb;
            }
            float* pa = g_xg + (r0 + m0 + 2 * p) * G_ + c0;
            float* pb = pa + G_;
            *(float4*)(pa)     = make_float4(lo[0], lo[1], lo[2],  lo[3]);
            *(float4*)(pa + 4) = make_float4(lo[4], lo[5], lo[6],  lo[7]);
            *(float4*)(pa + 8) = make_float4(lo[8], lo[9], lo[10], lo[11]);
            *(float4*)(pb)     = make_float4(hi[0], hi[1], hi[2],  hi[3]);
            *(float4*)(pb + 4) = make_float4(hi[4], hi[5], hi[6],  hi[7]);
            *(float4*)(pb + 8) = make_float4(hi[8], hi[9], hi[10], hi[11]);
        }
    }
}

// =====================================================================
// Kernel 2: recurrence. 128 CTAs x 32 batch rows, W_hh^T resident in smem.
// Thread tile: 4 rows x 12 cols (= 4 hidden units x 3 gates).
// =====================================================================
#define K2_SMEM ((128 * G_ + 128 * 36 + 2 * G_) * 4)   // 218112 B

__global__ __launch_bounds__(256, 1) void k2_recur(
    const float* __restrict__ Whh,
    const float* __restrict__ bhh,
    float* __restrict__ out,      // [B, T, H]
    float* __restrict__ hT_out)   // [B, H]
{
    extern __shared__ float sm[];
    float* Wt  = sm;                  // [128][384]  WhhT[k][col']
    float* hTm = Wt + 128 * G_;       // [128][36]   hT[k][m], padded
    float* bps = hTm + 128 * 36;      // [384] float pairs (2 floats each)

    const int tid = threadIdx.x;
    const size_t b0 = (size_t)blockIdx.x * 32;

    // Load W_hh reordered+transposed: Wt[k][j*3+gate] = Whh[gate*128+j][k]
    for (int idx = tid; idx < G_ * H_; idx += 256) {
        int g = idx >> 7, k = idx & 127;
        Wt[k * G_ + ((g & 127) * 3 + (g >> 7))] = Whh[idx];
    }
    for (int g = tid; g < G_; g += 256) {            // FIX: was `if (tid < G_)`
        int c = (g & 127) * 3 + (g >> 7);
        float b = bhh[g];
        bps[2 * c] = b; bps[2 * c + 1] = b;
    }
    for (int idx = tid; idx < 128 * 36; idx += 256) hTm[idx] = 0.0f;
    __syncthreads();

    const int mblk = tid & 7;     // 8 row blocks of 4
    const int jblk = tid >> 3;    // 32 col blocks of 12
    const int m0 = mblk * 4;
    const int c0 = jblk * 12;
    const int j0 = jblk * 4;

    unsigned long long bias[12];
    #pragma unroll
    for (int c = 0; c < 12; c++)
        bias[c] = *(const unsigned long long*)(bps + 2 * (c0 + c));

    float hprev[4][4];
    #pragma unroll
    for (int mi = 0; mi < 4; mi++)
        #pragma unroll
        for (int ji = 0; ji < 4; ji++) hprev[mi][ji] = 0.0f;

    for (int t = 0; t < T_; t++) {
        // Prefetch this step's input-side gate values
        float xf[4][12];
        #pragma unroll
        for (int mi = 0; mi < 4; mi++) {
            const float* p = g_xg + ((b0 + m0 + mi) * (size_t)T_ + t) * G_ + c0;
            float4 a = *(const float4*)(p);
            float4 b = *(const float4*)(p + 4);
            float4 c = *(const float4*)(p + 8);
            xf[mi][0] = a.x; xf[mi][1]  = a.y; xf[mi][2]  = a.z; xf[mi][3]  = a.w;
            xf[mi][4] = b.x; xf[mi][5]  = b.y; xf[mi][6]  = b.z; xf[mi][7]  = b.w;
            xf[mi][8] = c.x; xf[mi][9]  = c.y; xf[mi][10] = c.z; xf[mi][11] = c.w;
        }

        // hg = h @ W_hh^T + b_hh  (f32x2 microkernel, K=128)
        unsigned long long acc[2][12];
        #pragma unroll
        for (int c = 0; c < 12; c++) { acc[0][c] = bias[c]; acc[1][c] = bias[c]; }

        #pragma unroll 4
        for (int k = 0; k < 128; k++) {
            ulonglong2 hp = *(const ulonglong2*)(hTm + k * 36 + m0);
            const float* wrow = Wt + k * G_ + c0;
            float4 w0 = *(const float4*)(wrow);
            float4 w1 = *(const float4*)(wrow + 4);
            float4 w2 = *(const float4*)(wrow + 8);
            float wf[12] = {w0.x, w0.y, w0.z, w0.w,
                            w1.x, w1.y, w1.z, w1.w,
                            w2.x, w2.y, w2.z, w2.w};
            unsigned long long wp[12];
            #pragma unroll
            for (int c = 0; c < 12; c++) PACK2(wp[c], wf[c]);
            #pragma unroll
            for (int c = 0; c < 12; c++) {
                FMA2(acc[0][c], hp.x, wp[c]);   // rows m0, m0+1
                FMA2(acc[1][c], hp.y, wp[c]);   // rows m0+2, m0+3
            }
        }
        __syncthreads();   // all hTm reads done before anyone rewrites it

        // Unpack hg, elementwise GRU update (all in registers)
        float hg[4][12];
        #pragma unroll
        for (int p = 0; p < 2; p++)
            #pragma unroll
            for (int c = 0; c < 12; c++)
                UNPACK2(hg[2 * p][c], hg[2 * p + 1][c], acc[p][c]);

        #pragma unroll
        for (int mi = 0; mi < 4; mi++) {
            float o[4];
            #pragma unroll
            for (int ji = 0; ji < 4; ji++) {
                float r = sigmoidf_(xf[mi][ji * 3 + 0] + hg[mi][ji * 3 + 0]);
                float z = sigmoidf_(xf[mi][ji * 3 + 1] + hg[mi][ji * 3 + 1]);
                float n = tanhf_(xf[mi][ji * 3 + 2] + r * hg[mi][ji * 3 + 2]);
                float h = n + z * (hprev[mi][ji] - n);   // (1-z)*n + z*h
                hprev[mi][ji] = h;
                o[ji] = h;
            }
            *(float4*)(out + ((b0 + m0 + mi) * (size_t)T_ + t) * H_ + j0) =
                make_float4(o[0], o[1], o[2], o[3]);
        }

        // Publish new h into transposed smem tile
        #pragma unroll
        for (int ji = 0; ji < 4; ji++)
            *(float4*)(hTm + (j0 + ji) * 36 + m0) =
                make_float4(hprev[0][ji], hprev[1][ji], hprev[2][ji], hprev[3][ji]);
        __syncthreads();   // writes visible before next step's GEMM
    }

    // Final hidden state
    #pragma unroll
    for (int mi = 0; mi < 4; mi++)
        *(float4*)(hT_out + (b0 + m0 + mi) * H_ + j0) =
            make_float4(hprev[mi][0], hprev[mi][1], hprev[mi][2], hprev[mi][3]);
}

extern "C" void kernel_launch(void* const* d_in, const int* in_sizes, int n_in,
                              void* d_out, int out_size)
{
    const float* x   = (const float*)d_in[0];
    const float* Wih = (const float*)d_in[1];
    const float* Whh = (const float*)d_in[2];
    const float* bih = (const float*)d_in[3];
    const float* bhh = (const float*)d_in[4];

    float* out = (float*)d_out;                       // [B, T, H]
    float* hT  = out + (size_t)B_ * T_ * H_;          // [B, H]

    cudaFuncSetAttribute(k1_xgates, cudaFuncAttributeMaxDynamicSharedMemorySize, K1_SMEM);
    cudaFuncSetAttribute(k2_recur,  cudaFuncAttributeMaxDynamicSharedMemorySize, K2_SMEM);

    k1_xgates<<<(B_ * T_) / 128, 256, K1_SMEM>>>(x, Wih, bih);
    k2_recur<<<B_ / 32, 256, K2_SMEM>>>(Whh, bhh, out, hT);
}

// round 3
// speedup vs baseline: 1.0312x; 1.0312x over previous
#include <cuda_runtime.h>
#include <cstdint>

#define B_ 4096
#define T_ 120
#define I_ 64
#define H_ 128
#define G_ 384   // 3*H

// Scratch for input-side gate pre-activations, layout [t][B][G],
// gate-interleaved columns: col' = j*3 + gate, gate in {r=0,z=1,n=2}
__device__ float g_xg[(size_t)B_ * T_ * G_];

// ---- packed f32x2 helpers ----
#define FMA2(d, a, b) \
    asm("fma.rn.f32x2 %0, %1, %2, %0;" : "+l"(d) : "l"(a), "l"(b))

#define PACK2(p, f) do {                                            \
    unsigned int _u = __float_as_uint(f);                           \
    asm("mov.b64 %0, {%1, %2};" : "=l"(p) : "r"(_u), "r"(_u));      \
} while (0)

#define UNPACK2(lo, hi, p) do {                                     \
    unsigned int _l, _h;                                            \
    asm("mov.b64 {%0, %1}, %2;" : "=r"(_l), "=r"(_h) : "l"(p));     \
    (lo) = __uint_as_float(_l); (hi) = __uint_as_float(_h);         \
} while (0)

__device__ __forceinline__ float sigmoidf_(float x) {
    return __fdividef(1.0f, 1.0f + __expf(-x));
}
__device__ __forceinline__ float tanhf_(float x) {
    return 1.0f - __fdividef(2.0f, 1.0f + __expf(2.0f * x));
}

// =====================================================================
// Kernel 1: x_gates = x @ W_ih^T + b_ih  -> g_xg[t][B][G]
// CTA: 128 rows x 384 cols, 256 threads, tile 8 rows x 12 cols, 2 halves.
// Column-pair accumulators: w pairs load directly, h gets duplicated.
// =====================================================================
#define K1_SMEM ((64 * G_ + 64 * 132 + G_) * 4)

__global__ __launch_bounds__(256, 1) void k1_xgates(
    const float* __restrict__ x,
    const float* __restrict__ Wih,
    const float* __restrict__ bih)
{
    extern __shared__ float sm[];
    float* Wt = sm;               // [64][384]  WihT[i][col']
    float* xT = Wt + 64 * G_;     // [64][132]  xT[i][row]
    float* bI = xT + 64 * 132;    // [384] reordered bias

    const int tid = threadIdx.x;
    const size_t r0 = (size_t)blockIdx.x * 128;

    for (int idx = tid; idx < G_ * I_; idx += 256) {
        int g = idx >> 6, i = idx & 63;
        Wt[i * G_ + ((g & 127) * 3 + (g >> 7))] = Wih[idx];
    }
    for (int g = tid; g < G_; g += 256)
        bI[(g & 127) * 3 + (g >> 7)] = bih[g];
    for (int idx = tid; idx < 128 * I_; idx += 256) {
        int r = idx >> 6, i = idx & 63;
        xT[i * 132 + r] = x[(r0 + r) * I_ + i];
    }
    __syncthreads();

    const int mblk = tid & 15;       // 16 row blocks of 8
    const int jblk = tid >> 4;       // 16 col blocks of 12 (per half)
    const int m0 = mblk * 8;

    for (int half = 0; half < 2; half++) {
        const int c0 = half * 192 + jblk * 12;

        // acc[row][colpair]: lanes = (col 2c, col 2c+1); init with bias pairs
        unsigned long long acc[8][6];
        #pragma unroll
        for (int c = 0; c < 6; c++) {
            unsigned long long bp = *(const unsigned long long*)(bI + c0 + 2 * c);
            #pragma unroll
            for (int p = 0; p < 8; p++) acc[p][c] = bp;
        }

        #pragma unroll 4
        for (int k = 0; k < 64; k++) {
            const float* hrow = xT + k * 132 + m0;
            float4 ha = *(const float4*)(hrow);
            float4 hb = *(const float4*)(hrow + 4);
            unsigned long long hp[8];
            PACK2(hp[0], ha.x); PACK2(hp[1], ha.y);
            PACK2(hp[2], ha.z); PACK2(hp[3], ha.w);
            PACK2(hp[4], hb.x); PACK2(hp[5], hb.y);
            PACK2(hp[6], hb.z); PACK2(hp[7], hb.w);
            const float* wrow = Wt + k * G_ + c0;
            ulonglong2 wa = *(const ulonglong2*)(wrow);      // cols 0..3
            ulonglong2 wb = *(const ulonglong2*)(wrow + 4);  // cols 4..7
            ulonglong2 wc = *(const ulonglong2*)(wrow + 8);  // cols 8..11
            unsigned long long wp[6] = {wa.x, wa.y, wb.x, wb.y, wc.x, wc.y};
            #pragma unroll
            for (int p = 0; p < 8; p++) {
                #pragma unroll
                for (int c = 0; c < 6; c++) FMA2(acc[p][c], hp[p], wp[c]);
            }
        }

        // Epilogue: unpack (cols adjacent) and store to [t][B][G] layout
        #pragma unroll
        for (int p = 0; p < 8; p++) {
            float v[12];
            #pragma unroll
            for (int c = 0; c < 6; c++) UNPACK2(v[2 * c], v[2 * c + 1], acc[p][c]);
            unsigned int r = (unsigned int)(r0 + m0 + p);
            unsigned int b = r / T_, t = r % T_;
            float* dst = g_xg + ((size_t)t * B_ + b) * G_ + c0;
            *(float4*)(dst)     = make_float4(v[0], v[1], v[2],  v[3]);
            *(float4*)(dst + 4) = make_float4(v[4], v[5], v[6],  v[7]);
            *(float4*)(dst + 8) = make_float4(v[8], v[9], v[10], v[11]);
        }
    }
}

// =====================================================================
// Kernel 2: recurrence. 128 CTAs x 32 batch rows, W_hh^T resident in smem.
// Thread tile: 4 rows x 12 cols, column-pair accumulators.
// =====================================================================
#define K2_SMEM ((128 * G_ + 128 * 36 + G_) * 4)

__global__ __launch_bounds__(256, 1) void k2_recur(
    const float* __restrict__ Whh,
    const float* __restrict__ bhh,
    float* __restrict__ out,      // [B, T, H]
    float* __restrict__ hT_out)   // [B, H]
{
    extern __shared__ float sm[];
    float* Wt  = sm;                  // [128][384]  WhhT[k][col']
    float* hTm = Wt + 128 * G_;       // [128][36]   hT[k][m], padded
    float* bI  = hTm + 128 * 36;      // [384] reordered bias

    const int tid = threadIdx.x;
    const size_t b0 = (size_t)blockIdx.x * 32;

    for (int idx = tid; idx < G_ * H_; idx += 256) {
        int g = idx >> 7, k = idx & 127;
        Wt[k * G_ + ((g & 127) * 3 + (g >> 7))] = Whh[idx];
    }
    for (int g = tid; g < G_; g += 256)
        bI[(g & 127) * 3 + (g >> 7)] = bhh[g];
    for (int idx = tid; idx < 128 * 36; idx += 256) hTm[idx] = 0.0f;
    __syncthreads();

    const int mblk = tid & 7;     // 8 row blocks of 4
    const int jblk = tid >> 3;    // 32 col blocks of 12
    const int m0 = mblk * 4;
    const int c0 = jblk * 12;
    const int j0 = jblk * 4;

    unsigned long long bias[6];
    #pragma unroll
    for (int c = 0; c < 6; c++)
        bias[c] = *(const unsigned long long*)(bI + c0 + 2 * c);

    float hprev[4][4];
    #pragma unroll
    for (int mi = 0; mi < 4; mi++)
        #pragma unroll
        for (int ji = 0; ji < 4; ji++) hprev[mi][ji] = 0.0f;

    for (int t = 0; t < T_; t++) {
        // Prefetch input-side gate values (contiguous 48KB block per CTA-step)
        float xf[4][12];
        #pragma unroll
        for (int mi = 0; mi < 4; mi++) {
            const float* p = g_xg + ((size_t)t * B_ + (b0 + m0 + mi)) * G_ + c0;
            float4 a = *(const float4*)(p);
            float4 b = *(const float4*)(p + 4);
            float4 c = *(const float4*)(p + 8);
            xf[mi][0] = a.x; xf[mi][1]  = a.y; xf[mi][2]  = a.z; xf[mi][3]  = a.w;
            xf[mi][4] = b.x; xf[mi][5]  = b.y; xf[mi][6]  = b.z; xf[mi][7]  = b.w;
            xf[mi][8] = c.x; xf[mi][9]  = c.y; xf[mi][10] = c.z; xf[mi][11] = c.w;
        }

        // hg = h @ W_hh^T + b_hh; acc[row][colpair]
        unsigned long long acc[4][6];
        #pragma unroll
        for (int r = 0; r < 4; r++)
            #pragma unroll
            for (int c = 0; c < 6; c++) acc[r][c] = bias[c];

        #pragma unroll 4
        for (int k = 0; k < 128; k++) {
            float4 hv = *(const float4*)(hTm + k * 36 + m0);
            unsigned long long hp[4];
            PACK2(hp[0], hv.x); PACK2(hp[1], hv.y);
            PACK2(hp[2], hv.z); PACK2(hp[3], hv.w);
            const float* wrow = Wt + k * G_ + c0;
            ulonglong2 wa = *(const ulonglong2*)(wrow);
            ulonglong2 wb = *(const ulonglong2*)(wrow + 4);
            ulonglong2 wc = *(const ulonglong2*)(wrow + 8);
            unsigned long long wp[6] = {wa.x, wa.y, wb.x, wb.y, wc.x, wc.y};
            #pragma unroll
            for (int r = 0; r < 4; r++) {
                #pragma unroll
                for (int c = 0; c < 6; c++) FMA2(acc[r][c], hp[r], wp[c]);
            }
        }
        __syncthreads();   // all hTm reads done before anyone rewrites it

        float hg[4][12];
        #pragma unroll
        for (int r = 0; r < 4; r++)
            #pragma unroll
            for (int c = 0; c < 6; c++)
                UNPACK2(hg[r][2 * c], hg[r][2 * c + 1], acc[r][c]);

        #pragma unroll
        for (int mi = 0; mi < 4; mi++) {
            float o[4];
            #pragma unroll
            for (int ji = 0; ji < 4; ji++) {
                float r = sigmoidf_(xf[mi][ji * 3 + 0] + hg[mi][ji * 3 + 0]);
                float z = sigmoidf_(xf[mi][ji * 3 + 1] + hg[mi][ji * 3 + 1]);
                float n = tanhf_(xf[mi][ji * 3 + 2] + r * hg[mi][ji * 3 + 2]);
                float h = n + z * (hprev[mi][ji] - n);
                hprev[mi][ji] = h;
                o[ji] = h;
            }
            *(float4*)(out + ((b0 + m0 + mi) * (size_t)T_ + t) * H_ + j0) =
                make_float4(o[0], o[1], o[2], o[3]);
        }

        #pragma unroll
        for (int ji = 0; ji < 4; ji++)
            *(float4*)(hTm + (j0 + ji) * 36 + m0) =
                make_float4(hprev[0][ji], hprev[1][ji], hprev[2][ji], hprev[3][ji]);
        __syncthreads();
    }

    #pragma unroll
    for (int mi = 0; mi < 4; mi++)
        *(float4*)(hT_out + (b0 + m0 + mi) * H_ + j0) =
            make_float4(hprev[mi][0], hprev[mi][1], hprev[mi][2], hprev[mi][3]);
}

extern "C" void kernel_launch(void* const* d_in, const int* in_sizes, int n_in,
                              void* d_out, int out_size)
{
    const float* x   = (const float*)d_in[0];
    const float* Wih = (const float*)d_in[1];
    const float* Whh = (const float*)d_in[2];
    const float* bih = (const float*)d_in[3];
    const float* bhh = (const float*)d_in[4];

    float* out = (float*)d_out;                       // [B, T, H]
    float* hT  = out + (size_t)B_ * T_ * H_;          // [B, H]

    cudaFuncSetAttribute(k1_xgates, cudaFuncAttributeMaxDynamicSharedMemorySize, K1_SMEM);
    cudaFuncSetAttribute(k2_recur,  cudaFuncAttributeMaxDynamicSharedMemorySize, K2_SMEM);

    k1_xgates<<<(B_ * T_) / 128, 256, K1_SMEM>>>(x, Wih, bih);
    k2_recur<<<B_ / 32, 256, K2_SMEM>>>(Whh, bhh, out, hT);
}